// round 7
// baseline (speedup 1.0000x reference)
#include <cuda_runtime.h>
#include <cstdint>

#define B_   2
#define T_   2048
#define C_   2048
#define NH   16
#define NKV  4
#define HD   128
#define MROWS (B_*T_)          // 4096
#define KVC  (NKV*HD)          // 1024
#define QKVN (C_ + 2*KVC)      // 4096 (q | k | v)

__device__ float g_qkv[MROWS * QKVN];
__device__ float g_y[MROWS * C_];
__device__ float g_xr[MROWS * C_];
__device__ float g_wqkv[QKVN * C_];
__device__ float g_wo[C_ * C_];

// ---------------------------------------------------------------------------
__device__ __forceinline__ uint32_t smem_u32(const void* p) {
    uint32_t a;
    asm("{ .reg .u64 t; cvta.to.shared.u64 t, %1; cvt.u32.u64 %0, t; }" : "=r"(a) : "l"(p));
    return a;
}
__device__ __forceinline__ float tf32r(float x) {
    uint32_t u;
    asm("cvt.rna.tf32.f32 %0, %1;" : "=r"(u) : "f"(x));
    return __uint_as_float(u);
}
#define CPA16(s, g) asm volatile("cp.async.cg.shared.global [%0], [%1], 16;" :: "r"(s), "l"(g) : "memory")
#define CPA_COMMIT() asm volatile("cp.async.commit_group;" ::: "memory")
#define CPA_WAIT2()  asm volatile("cp.async.wait_group 2;" ::: "memory")
#define LDSM4(r0, r1, r2, r3, a) \
    asm volatile("ldmatrix.sync.aligned.m8n8.x4.shared.b16 {%0,%1,%2,%3}, [%4];" \
                 : "=r"(r0), "=r"(r1), "=r"(r2), "=r"(r3) : "r"(a))

__device__ __forceinline__ void mma16n8k8(float d[4], const uint32_t a[4], const uint32_t b[2]) {
    asm volatile(
        "mma.sync.aligned.m16n8k8.row.col.f32.tf32.tf32.f32 "
        "{%0,%1,%2,%3}, {%4,%5,%6,%7}, {%8,%9}, {%0,%1,%2,%3};"
        : "+f"(d[0]), "+f"(d[1]), "+f"(d[2]), "+f"(d[3])
        : "r"(a[0]), "r"(a[1]), "r"(a[2]), "r"(a[3]), "r"(b[0]), "r"(b[1]));
}

// ---------------------------------------------------------------------------
// tf32 tensor-core GEMM: C[M,N] = A[M,K]*B[N,K]^T, fp32 in/out (pre-rounded).
// 128x256 block, 8 warps (warp tile 64x64), KT=32, 4-stage cp.async ring with
// ONE barrier per K-iter, ldmatrix fragment loads.
// mode=1: fused RoPE (cols<3072) + tf32 rounding of output (QKV projection).
// ---------------------------------------------------------------------------
#define KT 32
#define TPITCH 36
#define A_TF (128 * TPITCH)                 // 4608 floats
#define B_TF (256 * TPITCH)                 // 9216 floats
#define STAGE_F (A_TF + B_TF)               // 13824 floats
#define STAGE_B (STAGE_F * 4)               // 55296 bytes
#define GEMM_SMEM (4 * STAGE_B)             // 221184 B

__device__ __forceinline__ void g_load_stage(uint32_t sdst,
        const float* __restrict__ A, const float* __restrict__ Bm,
        int m0, int n0, int k0, int K, int t)
{
#pragma unroll
    for (int i = 0; i < 4; i++) {
        int c = t + (i << 8);
        int row = c >> 3, q4 = c & 7;
        CPA16(sdst + (uint32_t)(row * TPITCH + q4 * 4) * 4,
              A + (size_t)(m0 + row) * K + k0 + (q4 << 2));
    }
#pragma unroll
    for (int i = 0; i < 8; i++) {
        int c = t + (i << 8);
        int row = c >> 3, q4 = c & 7;
        CPA16(sdst + (uint32_t)(A_TF + row * TPITCH + q4 * 4) * 4,
              Bm + (size_t)(n0 + row) * K + k0 + (q4 << 2));
    }
}

__global__ __launch_bounds__(256, 1)
void gemm_tc(const float* __restrict__ A, const float* __restrict__ Bm,
             float* __restrict__ Cm, int M, int N, int K, int mode,
             const float* __restrict__ fc, const float* __restrict__ fs)
{
    extern __shared__ __align__(16) float sm[];
    const uint32_t sbase = smem_u32(sm);
    const int t = threadIdx.x, wid = t >> 5, lane = t & 31;
    const int q = lane >> 2, tq = lane & 3;
    const int wm = wid & 1, wn = wid >> 1;           // 2(m) x 4(n) warps
    const int m0 = blockIdx.y * 128, n0 = blockIdx.x * 256;

    // per-thread ldmatrix base byte-offsets within a stage
    const int lg = lane >> 3, lr = lane & 7;
    const uint32_t aOff = (uint32_t)(((wm * 64 + lr + (lg & 1) * 8) * TPITCH + (lg >> 1) * 4) * 4);
    const uint32_t bOff = (uint32_t)((A_TF + (wn * 64 + lr + (lg >> 1) * 8) * TPITCH + (lg & 1) * 4) * 4);

    float d[4][8][4];
#pragma unroll
    for (int mi = 0; mi < 4; mi++)
#pragma unroll
        for (int ni = 0; ni < 8; ni++)
#pragma unroll
            for (int r = 0; r < 4; r++) d[mi][ni][r] = 0.0f;

#pragma unroll
    for (int s = 0; s < 3; s++) {
        g_load_stage(sbase + (uint32_t)s * STAGE_B, A, Bm, m0, n0, s * KT, K, t);
        CPA_COMMIT();
    }

    const int NK = K / KT;                           // 64
    for (int it = 0; it < NK; it++) {
        CPA_WAIT2();
        __syncthreads();
        const int itp = it + 3;
        if (itp < NK)
            g_load_stage(sbase + (uint32_t)(itp & 3) * STAGE_B, A, Bm, m0, n0, itp * KT, K, t);
        CPA_COMMIT();

        const uint32_t sOff = sbase + (uint32_t)(it & 3) * STAGE_B;
#pragma unroll
        for (int kk = 0; kk < 4; kk++) {
            uint32_t af[4][4];
#pragma unroll
            for (int mi = 0; mi < 4; mi++)
                LDSM4(af[mi][0], af[mi][1], af[mi][2], af[mi][3],
                      sOff + aOff + (uint32_t)(mi * 16 * TPITCH * 4 + kk * 32));
            uint32_t bf[8][2];
#pragma unroll
            for (int np = 0; np < 4; np++)
                LDSM4(bf[2 * np][0], bf[2 * np][1], bf[2 * np + 1][0], bf[2 * np + 1][1],
                      sOff + bOff + (uint32_t)(np * 16 * TPITCH * 4 + kk * 32));
#pragma unroll
            for (int mi = 0; mi < 4; mi++)
#pragma unroll
                for (int ni = 0; ni < 8; ni++)
                    mma16n8k8(d[mi][ni], af[mi], bf[ni]);
        }
    }

    // epilogue
#pragma unroll
    for (int mi = 0; mi < 4; mi++) {
        int row = m0 + wm * 64 + mi * 16 + q;
        int row2 = row + 8;
#pragma unroll
        for (int ni = 0; ni < 8; ni++) {
            int col = n0 + wn * 64 + ni * 8 + 2 * tq;
            float v0 = d[mi][ni][0], v1 = d[mi][ni][1];
            float v2 = d[mi][ni][2], v3 = d[mi][ni][3];
            if (mode) {
                if (col < C_ + KVC) {
                    int i = (col & 127) >> 1;
                    int tp1 = row & (T_ - 1), tp2 = row2 & (T_ - 1);
                    float c1 = fc[tp1 * 64 + i], s1 = fs[tp1 * 64 + i];
                    float c2 = fc[tp2 * 64 + i], s2 = fs[tp2 * 64 + i];
                    float r0 = v0 * c1 - v1 * s1, r1 = v0 * s1 + v1 * c1;
                    float r2 = v2 * c2 - v3 * s2, r3 = v2 * s2 + v3 * c2;
                    v0 = r0; v1 = r1; v2 = r2; v3 = r3;
                }
                v0 = tf32r(v0); v1 = tf32r(v1);
                v2 = tf32r(v2); v3 = tf32r(v3);
            }
            *(float2*)(Cm + (size_t)row  * N + col) = make_float2(v0, v1);
            *(float2*)(Cm + (size_t)row2 * N + col) = make_float2(v2, v3);
        }
    }
}

// ---------------------------------------------------------------------------
__global__ __launch_bounds__(256)
void tf32_round(const float4* __restrict__ in, float4* __restrict__ out, int n4)
{
    for (int i = blockIdx.x * 256 + threadIdx.x; i < n4; i += gridDim.x * 256) {
        float4 v = in[i];
        v.x = tf32r(v.x); v.y = tf32r(v.y); v.z = tf32r(v.z); v.w = tf32r(v.w);
        out[i] = v;
    }
}

// ---------------------------------------------------------------------------
// Flash attention on mma.sync tf32 (round-5/6 passing kernel; reads g_qkv).
// ---------------------------------------------------------------------------
#define BM 128
#define BN 64
#define QP 132
#define KP 132
#define PP 68
#define ATT_SMEM ((128*QP + 64*KP + 64*KP + 128*PP) * 4)

__global__ __launch_bounds__(256, 1)
void attn_mma()
{
    extern __shared__ __align__(16) float smA[];
    float* Qs = smA;
    float* Ks = Qs + 128 * QP;
    float* Vs = Ks + 64 * KP;
    float* Ps = Vs + 64 * KP;

    const int t = threadIdx.x, w = t >> 5, lane = t & 31;
    const int q = lane >> 2, tq = lane & 3;
    const int qb = (int)gridDim.x - 1 - (int)blockIdx.x;
    const int h = blockIdx.y, b = blockIdx.z;
    const int kvh = h >> 2;
    const float scale = 0.08838834764831845f;
    const int wr = w * 16;

    {
        const float* qbase = g_qkv + ((size_t)(b * T_ + qb * BM)) * QKVN + h * HD;
#pragma unroll
        for (int i = 0; i < 16; i++) {
            int f = t + (i << 8);
            int row = f >> 5, d4 = f & 31;
            *(float4*)(Qs + row * QP + (d4 << 2)) =
                *(const float4*)(qbase + (size_t)row * QKVN + (d4 << 2));
        }
    }

    float o[16][4];
#pragma unroll
    for (int nf = 0; nf < 16; nf++)
#pragma unroll
        for (int r = 0; r < 4; r++) o[nf][r] = 0.0f;
    float m0 = -1e30f, m1 = -1e30f, l0 = 0.0f, l1 = 0.0f;

    const int ntiles = 2 * qb + 2;
    for (int kb = 0; kb < ntiles; kb++) {
        __syncthreads();
        {
            const float* kbase = g_qkv + ((size_t)(b * T_ + kb * BN)) * QKVN + C_ + kvh * HD;
            const float* vbase = g_qkv + ((size_t)(b * T_ + kb * BN)) * QKVN + C_ + KVC + kvh * HD;
#pragma unroll
            for (int i = 0; i < 8; i++) {
                int f = t + (i << 8);
                int row = f >> 5, d4 = f & 31;
                *(float4*)(Ks + row * KP + (d4 << 2)) =
                    *(const float4*)(kbase + (size_t)row * QKVN + (d4 << 2));
                *(float4*)(Vs + row * KP + (d4 << 2)) =
                    *(const float4*)(vbase + (size_t)row * QKVN + (d4 << 2));
            }
        }
        __syncthreads();

        float s[8][4];
#pragma unroll
        for (int nf = 0; nf < 8; nf++)
#pragma unroll
            for (int r = 0; r < 4; r++) s[nf][r] = 0.0f;

#pragma unroll
        for (int ks = 0; ks < 16; ks++) {
            uint32_t a[4];
            const uint32_t* qp = (const uint32_t*)(Qs + (wr + q) * QP + ks * 8 + tq);
            a[0] = qp[0]; a[1] = qp[8 * QP]; a[2] = qp[4]; a[3] = qp[8 * QP + 4];
#pragma unroll
            for (int nf = 0; nf < 8; nf++) {
                const uint32_t* kp = (const uint32_t*)(Ks + (nf * 8 + q) * KP + ks * 8 + tq);
                uint32_t bb[2] = {kp[0], kp[4]};
                mma16n8k8(s[nf], a, bb);
            }
        }

#pragma unroll
        for (int nf = 0; nf < 8; nf++)
#pragma unroll
            for (int r = 0; r < 4; r++) s[nf][r] *= scale;

        if (kb >= 2 * qb) {
            int ig0 = qb * BM + wr + q, ig1 = ig0 + 8;
#pragma unroll
            for (int nf = 0; nf < 8; nf++) {
                int jg = kb * BN + nf * 8 + 2 * tq;
                if (jg     > ig0) s[nf][0] = -1e30f;
                if (jg + 1 > ig0) s[nf][1] = -1e30f;
                if (jg     > ig1) s[nf][2] = -1e30f;
                if (jg + 1 > ig1) s[nf][3] = -1e30f;
            }
        }

        float mx0 = s[0][0], mx1 = s[0][2];
#pragma unroll
        for (int nf = 0; nf < 8; nf++) {
            mx0 = fmaxf(mx0, fmaxf(s[nf][0], s[nf][1]));
            mx1 = fmaxf(mx1, fmaxf(s[nf][2], s[nf][3]));
        }
        mx0 = fmaxf(mx0, __shfl_xor_sync(0xffffffffu, mx0, 1));
        mx0 = fmaxf(mx0, __shfl_xor_sync(0xffffffffu, mx0, 2));
        mx1 = fmaxf(mx1, __shfl_xor_sync(0xffffffffu, mx1, 1));
        mx1 = fmaxf(mx1, __shfl_xor_sync(0xffffffffu, mx1, 2));
        float mn0 = fmaxf(m0, mx0), mn1 = fmaxf(m1, mx1);
        float c0 = __expf(m0 - mn0), c1 = __expf(m1 - mn1);
        float rs0 = 0.0f, rs1 = 0.0f;
#pragma unroll
        for (int nf = 0; nf < 8; nf++) {
            s[nf][0] = __expf(s[nf][0] - mn0);
            s[nf][1] = __expf(s[nf][1] - mn0);
            s[nf][2] = __expf(s[nf][2] - mn1);
            s[nf][3] = __expf(s[nf][3] - mn1);
            rs0 += s[nf][0] + s[nf][1];
            rs1 += s[nf][2] + s[nf][3];
        }
        rs0 += __shfl_xor_sync(0xffffffffu, rs0, 1);
        rs0 += __shfl_xor_sync(0xffffffffu, rs0, 2);
        rs1 += __shfl_xor_sync(0xffffffffu, rs1, 1);
        rs1 += __shfl_xor_sync(0xffffffffu, rs1, 2);
        l0 = l0 * c0 + rs0;  l1 = l1 * c1 + rs1;
        m0 = mn0;  m1 = mn1;
#pragma unroll
        for (int nf = 0; nf < 16; nf++) {
            o[nf][0] *= c0; o[nf][1] *= c0;
            o[nf][2] *= c1; o[nf][3] *= c1;
        }

#pragma unroll
        for (int nf = 0; nf < 8; nf++) {
            *(float2*)(Ps + (wr + q) * PP + nf * 8 + 2 * tq) =
                make_float2(tf32r(s[nf][0]), tf32r(s[nf][1]));
            *(float2*)(Ps + (wr + q + 8) * PP + nf * 8 + 2 * tq) =
                make_float2(tf32r(s[nf][2]), tf32r(s[nf][3]));
        }
        __syncwarp();

#pragma unroll
        for (int ks = 0; ks < 8; ks++) {
            uint32_t a[4];
            const uint32_t* pp = (const uint32_t*)(Ps + (wr + q) * PP + ks * 8 + tq);
            a[0] = pp[0]; a[1] = pp[8 * PP]; a[2] = pp[4]; a[3] = pp[8 * PP + 4];
#pragma unroll
            for (int nf = 0; nf < 16; nf++) {
                const uint32_t* vp = (const uint32_t*)(Vs + (ks * 8 + tq) * KP + nf * 8 + q);
                uint32_t bb[2] = {vp[0], vp[4 * KP]};
                mma16n8k8(o[nf], a, bb);
            }
        }
    }

    float i0 = 1.0f / l0, i1 = 1.0f / l1;
    int r0 = qb * BM + wr + q;
    float* yb = g_y + ((size_t)(b * T_ + r0)) * C_ + h * HD;
#pragma unroll
    for (int nf = 0; nf < 16; nf++) {
        *(float2*)(yb + nf * 8 + 2 * tq) =
            make_float2(tf32r(o[nf][0] * i0), tf32r(o[nf][1] * i0));
        *(float2*)(yb + 8 * C_ + nf * 8 + 2 * tq) =
            make_float2(tf32r(o[nf][2] * i1), tf32r(o[nf][3] * i1));
    }
}

// ---------------------------------------------------------------------------
extern "C" void kernel_launch(void* const* d_in, const int* in_sizes, int n_in,
                              void* d_out, int out_size)
{
    const float* x  = (const float*)d_in[0];
    const float* fc = (const float*)d_in[1];
    const float* fs = (const float*)d_in[2];
    const float* wq = (const float*)d_in[3];
    const float* wk = (const float*)d_in[4];
    const float* wv = (const float*)d_in[5];
    const float* wo = (const float*)d_in[6];
    float* out = (float*)d_out;

    float *qkv, *y, *xr, *wqkv, *rwo;
    cudaGetSymbolAddress((void**)&qkv,  g_qkv);
    cudaGetSymbolAddress((void**)&y,    g_y);
    cudaGetSymbolAddress((void**)&xr,   g_xr);
    cudaGetSymbolAddress((void**)&wqkv, g_wqkv);
    cudaGetSymbolAddress((void**)&rwo,  g_wo);

    tf32_round<<<2048, 256>>>((const float4*)x,  (float4*)xr, MROWS * C_ / 4);
    tf32_round<<<1024, 256>>>((const float4*)wq, (float4*)wqkv, C_ * C_ / 4);
    tf32_round<<<512,  256>>>((const float4*)wk, (float4*)(wqkv + (size_t)C_ * C_), KVC * C_ / 4);
    tf32_round<<<512,  256>>>((const float4*)wv, (float4*)(wqkv + (size_t)(C_ + KVC) * C_), KVC * C_ / 4);
    tf32_round<<<1024, 256>>>((const float4*)wo, (float4*)rwo, C_ * C_ / 4);

    cudaFuncSetAttribute(gemm_tc, cudaFuncAttributeMaxDynamicSharedMemorySize, GEMM_SMEM);

    // fused QKV projection + RoPE + tf32 rounding
    gemm_tc<<<dim3(QKVN / 256, MROWS / 128), 256, GEMM_SMEM>>>(
        xr, wqkv, qkv, MROWS, QKVN, C_, 1, fc, fs);

    cudaFuncSetAttribute(attn_mma, cudaFuncAttributeMaxDynamicSharedMemorySize, ATT_SMEM);
    attn_mma<<<dim3(T_ / BM, NH, B_), 256, ATT_SMEM>>>();

    // output projection
    gemm_tc<<<dim3(C_ / 256, MROWS / 128), 256, GEMM_SMEM>>>(
        y, rwo, out, MROWS, C_, C_, 0, nullptr, nullptr);
}

// round 10
// speedup vs baseline: 1.6014x; 1.6014x over previous
#include <cuda_runtime.h>
#include <cstdint>

#define B_   2
#define T_   2048
#define C_   2048
#define NH   16
#define NKV  4
#define HD   128
#define MROWS (B_*T_)          // 4096
#define KVC  (NKV*HD)          // 1024
#define QKVN (C_ + 2*KVC)      // 4096 (q | k | v)

__device__ float g_qkv[MROWS * QKVN];
__device__ float g_y[MROWS * C_];
__device__ float g_xr[MROWS * C_];
__device__ float g_wqkv[QKVN * C_];
__device__ float g_wo[C_ * C_];

// ---------------------------------------------------------------------------
__device__ __forceinline__ uint32_t smem_u32(const void* p) {
    uint32_t a;
    asm("{ .reg .u64 t; cvta.to.shared.u64 t, %1; cvt.u32.u64 %0, t; }" : "=r"(a) : "l"(p));
    return a;
}
__device__ __forceinline__ float tf32r(float x) {
    uint32_t u;
    asm("cvt.rna.tf32.f32 %0, %1;" : "=r"(u) : "f"(x));
    return __uint_as_float(u);
}
#define CPA16(s, g) asm volatile("cp.async.cg.shared.global [%0], [%1], 16;" :: "r"(s), "l"(g) : "memory")
#define CPA_COMMIT() asm volatile("cp.async.commit_group;" ::: "memory")
#define CPA_WAIT2()  asm volatile("cp.async.wait_group 2;" ::: "memory")

__device__ __forceinline__ void mma16n8k8(float d[4], const uint32_t a[4], const uint32_t b[2]) {
    asm volatile(
        "mma.sync.aligned.m16n8k8.row.col.f32.tf32.tf32.f32 "
        "{%0,%1,%2,%3}, {%4,%5,%6,%7}, {%8,%9}, {%0,%1,%2,%3};"
        : "+f"(d[0]), "+f"(d[1]), "+f"(d[2]), "+f"(d[3])
        : "r"(a[0]), "r"(a[1]), "r"(a[2]), "r"(a[3]), "r"(b[0]), "r"(b[1]));
}

// ---------------------------------------------------------------------------
// tf32 tensor-core GEMM: C[M,N] = A[M,K]*B[N,K]^T, fp32 in/out (pre-rounded).
// 128x256 block, 8 warps (warp tile 64x64), KT=32.
// Round-6 body; only change: 4-stage ring -> single barrier per K-iter.
// mode=1: fused RoPE (cols<3072) + tf32 rounding of output (QKV projection).
// ---------------------------------------------------------------------------
#define KT 32
#define TPITCH 36
#define A_TF (128 * TPITCH)                 // 4608 floats
#define B_TF (256 * TPITCH)                 // 9216 floats
#define STAGE_F (A_TF + B_TF)               // 13824 floats
#define STAGE_B (STAGE_F * 4)               // 55296 bytes
#define GEMM_SMEM (4 * STAGE_B)             // 221184 B

__device__ __forceinline__ void g_load_stage(uint32_t sdst,
        const float* __restrict__ A, const float* __restrict__ Bm,
        int m0, int n0, int k0, int K, int t)
{
#pragma unroll
    for (int i = 0; i < 4; i++) {
        int c = t + (i << 8);
        int row = c >> 3, q4 = c & 7;
        CPA16(sdst + (uint32_t)(row * TPITCH + q4 * 4) * 4,
              A + (size_t)(m0 + row) * K + k0 + (q4 << 2));
    }
#pragma unroll
    for (int i = 0; i < 8; i++) {
        int c = t + (i << 8);
        int row = c >> 3, q4 = c & 7;
        CPA16(sdst + (uint32_t)(A_TF + row * TPITCH + q4 * 4) * 4,
              Bm + (size_t)(n0 + row) * K + k0 + (q4 << 2));
    }
}

__global__ __launch_bounds__(256, 1)
void gemm_tc(const float* __restrict__ A, const float* __restrict__ Bm,
             float* __restrict__ Cm, int M, int N, int K, int mode,
             const float* __restrict__ fc, const float* __restrict__ fs)
{
    extern __shared__ __align__(16) float sm[];
    const uint32_t sbase = smem_u32(sm);
    const int t = threadIdx.x, wid = t >> 5, lane = t & 31;
    const int q = lane >> 2, tq = lane & 3;
    const int wm = wid & 1, wn = wid >> 1;           // 2(m) x 4(n) warps
    const int m0 = blockIdx.y * 128, n0 = blockIdx.x * 256;

    float d[4][8][4];
#pragma unroll
    for (int mi = 0; mi < 4; mi++)
#pragma unroll
        for (int ni = 0; ni < 8; ni++)
#pragma unroll
            for (int r = 0; r < 4; r++) d[mi][ni][r] = 0.0f;

#pragma unroll
    for (int s = 0; s < 3; s++) {
        g_load_stage(sbase + (uint32_t)s * STAGE_B, A, Bm, m0, n0, s * KT, K, t);
        CPA_COMMIT();
    }

    const int NK = K / KT;                           // 64
    for (int it = 0; it < NK; it++) {
        CPA_WAIT2();
        __syncthreads();
        const float* As = sm + (it & 3) * STAGE_F;
        const float* Bs = As + A_TF;

#pragma unroll
        for (int kk = 0; kk < 4; kk++) {
            uint32_t af[4][4];
#pragma unroll
            for (int mi = 0; mi < 4; mi++) {
                const float* ap = As + (wm * 64 + mi * 16 + q) * TPITCH + kk * 8 + tq;
                af[mi][0] = __float_as_uint(ap[0]);
                af[mi][1] = __float_as_uint(ap[8 * TPITCH]);
                af[mi][2] = __float_as_uint(ap[4]);
                af[mi][3] = __float_as_uint(ap[8 * TPITCH + 4]);
            }
            uint32_t bf[8][2];
#pragma unroll
            for (int ni = 0; ni < 8; ni++) {
                const float* bp = Bs + (wn * 64 + ni * 8 + q) * TPITCH + kk * 8 + tq;
                bf[ni][0] = __float_as_uint(bp[0]);
                bf[ni][1] = __float_as_uint(bp[4]);
            }
#pragma unroll
            for (int mi = 0; mi < 4; mi++)
#pragma unroll
                for (int ni = 0; ni < 8; ni++)
                    mma16n8k8(d[mi][ni], af[mi], bf[ni]);
        }
        // 4-stage ring: stage (it+3)&3 was last read at iter it-1, before this
        // iter's barrier -> safe to overwrite without a second barrier.
        const int itp = it + 3;
        if (itp < NK)
            g_load_stage(sbase + (uint32_t)(itp & 3) * STAGE_B, A, Bm, m0, n0, itp * KT, K, t);
        CPA_COMMIT();
    }

    // epilogue
#pragma unroll
    for (int mi = 0; mi < 4; mi++) {
        int row = m0 + wm * 64 + mi * 16 + q;
        int row2 = row + 8;
#pragma unroll
        for (int ni = 0; ni < 8; ni++) {
            int col = n0 + wn * 64 + ni * 8 + 2 * tq;
            float v0 = d[mi][ni][0], v1 = d[mi][ni][1];
            float v2 = d[mi][ni][2], v3 = d[mi][ni][3];
            if (mode) {
                if (col < C_ + KVC) {
                    int i = (col & 127) >> 1;
                    int tp1 = row & (T_ - 1), tp2 = row2 & (T_ - 1);
                    float c1 = fc[tp1 * 64 + i], s1 = fs[tp1 * 64 + i];
                    float c2 = fc[tp2 * 64 + i], s2 = fs[tp2 * 64 + i];
                    float r0 = v0 * c1 - v1 * s1, r1 = v0 * s1 + v1 * c1;
                    float r2 = v2 * c2 - v3 * s2, r3 = v2 * s2 + v3 * c2;
                    v0 = r0; v1 = r1; v2 = r2; v3 = r3;
                }
                v0 = tf32r(v0); v1 = tf32r(v1);
                v2 = tf32r(v2); v3 = tf32r(v3);
            }
            *(float2*)(Cm + (size_t)row  * N + col) = make_float2(v0, v1);
            *(float2*)(Cm + (size_t)row2 * N + col) = make_float2(v2, v3);
        }
    }
}

// ---------------------------------------------------------------------------
__global__ __launch_bounds__(256)
void tf32_round(const float4* __restrict__ in, float4* __restrict__ out, int n4)
{
    for (int i = blockIdx.x * 256 + threadIdx.x; i < n4; i += gridDim.x * 256) {
        float4 v = in[i];
        v.x = tf32r(v.x); v.y = tf32r(v.y); v.z = tf32r(v.z); v.w = tf32r(v.w);
        out[i] = v;
    }
}

// ---------------------------------------------------------------------------
// Flash attention on mma.sync tf32 (round-6 kernel + Q fragments hoisted
// into registers: Q smem is read once, QK mainloop has no Q LDS).
// ---------------------------------------------------------------------------
#define BM 128
#define BN 64
#define QP 132
#define KP 132
#define PP 68
#define ATT_SMEM ((128*QP + 64*KP + 64*KP + 128*PP) * 4)

__global__ __launch_bounds__(256, 1)
void attn_mma()
{
    extern __shared__ __align__(16) float smA[];
    float* Qs = smA;
    float* Ks = Qs + 128 * QP;
    float* Vs = Ks + 64 * KP;
    float* Ps = Vs + 64 * KP;

    const int t = threadIdx.x, w = t >> 5, lane = t & 31;
    const int q = lane >> 2, tq = lane & 3;
    const int qb = (int)gridDim.x - 1 - (int)blockIdx.x;
    const int h = blockIdx.y, b = blockIdx.z;
    const int kvh = h >> 2;
    const float scale = 0.08838834764831845f;
    const int wr = w * 16;

    {
        const float* qbase = g_qkv + ((size_t)(b * T_ + qb * BM)) * QKVN + h * HD;
#pragma unroll
        for (int i = 0; i < 16; i++) {
            int f = t + (i << 8);
            int row = f >> 5, d4 = f & 31;
            *(float4*)(Qs + row * QP + (d4 << 2)) =
                *(const float4*)(qbase + (size_t)row * QKVN + (d4 << 2));
        }
    }
    __syncthreads();

    // hoist Q fragments into registers (64 regs), one-time read
    uint32_t qf[16][4];
#pragma unroll
    for (int ks = 0; ks < 16; ks++) {
        const uint32_t* qp = (const uint32_t*)(Qs + (wr + q) * QP + ks * 8 + tq);
        qf[ks][0] = qp[0]; qf[ks][1] = qp[8 * QP];
        qf[ks][2] = qp[4]; qf[ks][3] = qp[8 * QP + 4];
    }

    float o[16][4];
#pragma unroll
    for (int nf = 0; nf < 16; nf++)
#pragma unroll
        for (int r = 0; r < 4; r++) o[nf][r] = 0.0f;
    float m0 = -1e30f, m1 = -1e30f, l0 = 0.0f, l1 = 0.0f;

    const int ntiles = 2 * qb + 2;
    for (int kb = 0; kb < ntiles; kb++) {
        __syncthreads();
        {
            const float* kbase = g_qkv + ((size_t)(b * T_ + kb * BN)) * QKVN + C_ + kvh * HD;
            const float* vbase = g_qkv + ((size_t)(b * T_ + kb * BN)) * QKVN + C_ + KVC + kvh * HD;
#pragma unroll
            for (int i = 0; i < 8; i++) {
                int f = t + (i << 8);
                int row = f >> 5, d4 = f & 31;
                *(float4*)(Ks + row * KP + (d4 << 2)) =
                    *(const float4*)(kbase + (size_t)row * QKVN + (d4 << 2));
                *(float4*)(Vs + row * KP + (d4 << 2)) =
                    *(const float4*)(vbase + (size_t)row * QKVN + (d4 << 2));
            }
        }
        __syncthreads();

        float s[8][4];
#pragma unroll
        for (int nf = 0; nf < 8; nf++)
#pragma unroll
            for (int r = 0; r < 4; r++) s[nf][r] = 0.0f;

#pragma unroll
        for (int ks = 0; ks < 16; ks++) {
#pragma unroll
            for (int nf = 0; nf < 8; nf++) {
                const uint32_t* kp = (const uint32_t*)(Ks + (nf * 8 + q) * KP + ks * 8 + tq);
                uint32_t bb[2] = {kp[0], kp[4]};
                mma16n8k8(s[nf], qf[ks], bb);
            }
        }

#pragma unroll
        for (int nf = 0; nf < 8; nf++)
#pragma unroll
            for (int r = 0; r < 4; r++) s[nf][r] *= scale;

        if (kb >= 2 * qb) {
            int ig0 = qb * BM + wr + q, ig1 = ig0 + 8;
#pragma unroll
            for (int nf = 0; nf < 8; nf++) {
                int jg = kb * BN + nf * 8 + 2 * tq;
                if (jg     > ig0) s[nf][0] = -1e30f;
                if (jg + 1 > ig0) s[nf][1] = -1e30f;
                if (jg     > ig1) s[nf][2] = -1e30f;
                if (jg + 1 > ig1) s[nf][3] = -1e30f;
            }
        }

        float mx0 = s[0][0], mx1 = s[0][2];
#pragma unroll
        for (int nf = 0; nf < 8; nf++) {
            mx0 = fmaxf(mx0, fmaxf(s[nf][0], s[nf][1]));
            mx1 = fmaxf(mx1, fmaxf(s[nf][2], s[nf][3]));
        }
        mx0 = fmaxf(mx0, __shfl_xor_sync(0xffffffffu, mx0, 1));
        mx0 = fmaxf(mx0, __shfl_xor_sync(0xffffffffu, mx0, 2));
        mx1 = fmaxf(mx1, __shfl_xor_sync(0xffffffffu, mx1, 1));
        mx1 = fmaxf(mx1, __shfl_xor_sync(0xffffffffu, mx1, 2));
        float mn0 = fmaxf(m0, mx0), mn1 = fmaxf(m1, mx1);
        float c0 = __expf(m0 - mn0), c1 = __expf(m1 - mn1);
        float rs0 = 0.0f, rs1 = 0.0f;
#pragma unroll
        for (int nf = 0; nf < 8; nf++) {
            s[nf][0] = __expf(s[nf][0] - mn0);
            s[nf][1] = __expf(s[nf][1] - mn0);
            s[nf][2] = __expf(s[nf][2] - mn1);
            s[nf][3] = __expf(s[nf][3] - mn1);
            rs0 += s[nf][0] + s[nf][1];
            rs1 += s[nf][2] + s[nf][3];
        }
        rs0 += __shfl_xor_sync(0xffffffffu, rs0, 1);
        rs0 += __shfl_xor_sync(0xffffffffu, rs0, 2);
        rs1 += __shfl_xor_sync(0xffffffffu, rs1, 1);
        rs1 += __shfl_xor_sync(0xffffffffu, rs1, 2);
        l0 = l0 * c0 + rs0;  l1 = l1 * c1 + rs1;
        m0 = mn0;  m1 = mn1;
#pragma unroll
        for (int nf = 0; nf < 16; nf++) {
            o[nf][0] *= c0; o[nf][1] *= c0;
            o[nf][2] *= c1; o[nf][3] *= c1;
        }

#pragma unroll
        for (int nf = 0; nf < 8; nf++) {
            *(float2*)(Ps + (wr + q) * PP + nf * 8 + 2 * tq) =
                make_float2(tf32r(s[nf][0]), tf32r(s[nf][1]));
            *(float2*)(Ps + (wr + q + 8) * PP + nf * 8 + 2 * tq) =
                make_float2(tf32r(s[nf][2]), tf32r(s[nf][3]));
        }
        __syncwarp();

#pragma unroll
        for (int ks = 0; ks < 8; ks++) {
            uint32_t a[4];
            const uint32_t* pp = (const uint32_t*)(Ps + (wr + q) * PP + ks * 8 + tq);
            a[0] = pp[0]; a[1] = pp[8 * PP]; a[2] = pp[4]; a[3] = pp[8 * PP + 4];
#pragma unroll
            for (int nf = 0; nf < 16; nf++) {
                const uint32_t* vp = (const uint32_t*)(Vs + (ks * 8 + tq) * KP + nf * 8 + q);
                uint32_t bb[2] = {vp[0], vp[4 * KP]};
                mma16n8k8(o[nf], a, bb);
            }
        }
    }

    float i0 = 1.0f / l0, i1 = 1.0f / l1;
    int r0 = qb * BM + wr + q;
    float* yb = g_y + ((size_t)(b * T_ + r0)) * C_ + h * HD;
#pragma unroll
    for (int nf = 0; nf < 16; nf++) {
        *(float2*)(yb + nf * 8 + 2 * tq) =
            make_float2(tf32r(o[nf][0] * i0), tf32r(o[nf][1] * i0));
        *(float2*)(yb + 8 * C_ + nf * 8 + 2 * tq) =
            make_float2(tf32r(o[nf][2] * i1), tf32r(o[nf][3] * i1));
    }
}

// ---------------------------------------------------------------------------
extern "C" void kernel_launch(void* const* d_in, const int* in_sizes, int n_in,
                              void* d_out, int out_size)
{
    const float* x  = (const float*)d_in[0];
    const float* fc = (const float*)d_in[1];
    const float* fs = (const float*)d_in[2];
    const float* wq = (const float*)d_in[3];
    const float* wk = (const float*)d_in[4];
    const float* wv = (const float*)d_in[5];
    const float* wo = (const float*)d_in[6];
    float* out = (float*)d_out;

    float *qkv, *y, *xr, *wqkv, *rwo;
    cudaGetSymbolAddress((void**)&qkv,  g_qkv);
    cudaGetSymbolAddress((void**)&y,    g_y);
    cudaGetSymbolAddress((void**)&xr,   g_xr);
    cudaGetSymbolAddress((void**)&wqkv, g_wqkv);
    cudaGetSymbolAddress((void**)&rwo,  g_wo);

    tf32_round<<<2048, 256>>>((const float4*)x,  (float4*)xr, MROWS * C_ / 4);
    tf32_round<<<1024, 256>>>((const float4*)wq, (float4*)wqkv, C_ * C_ / 4);
    tf32_round<<<512,  256>>>((const float4*)wk, (float4*)(wqkv + (size_t)C_ * C_), KVC * C_ / 4);
    tf32_round<<<512,  256>>>((const float4*)wv, (float4*)(wqkv + (size_t)(C_ + KVC) * C_), KVC * C_ / 4);
    tf32_round<<<1024, 256>>>((const float4*)wo, (float4*)rwo, C_ * C_ / 4);

    cudaFuncSetAttribute(gemm_tc, cudaFuncAttributeMaxDynamicSharedMemorySize, GEMM_SMEM);

    // fused QKV projection + RoPE + tf32 rounding
    gemm_tc<<<dim3(QKVN / 256, MROWS / 128), 256, GEMM_SMEM>>>(
        xr, wqkv, qkv, MROWS, QKVN, C_, 1, fc, fs);

    cudaFuncSetAttribute(attn_mma, cudaFuncAttributeMaxDynamicSharedMemorySize, ATT_SMEM);
    attn_mma<<<dim3(T_ / BM, NH, B_), 256, ATT_SMEM>>>();

    // output projection
    gemm_tc<<<dim3(C_ / 256, MROWS / 128), 256, GEMM_SMEM>>>(
        y, rwo, out, MROWS, C_, C_, 0, nullptr, nullptr);
}